// round 1
// baseline (speedup 1.0000x reference)
#include <cuda_runtime.h>
#include <cuda_bf16.h>

// STN_fixTheta: fused 8x nearest-upsample + dual bilinear grid_sample.
// gt: [8,1,128,256] f32, theta: [8,6] f32.
// out: box [8,1,1024,2048] f32 followed by boxy [8,1,1024,2048] f32.

namespace {
constexpr int NB  = 8;
constexpr int HIN = 128;
constexpr int WIN = 256;
constexpr int HO  = 1024;
constexpr int WO  = 2048;

__global__ __launch_bounds__(256) void stn_kernel(
    const float* __restrict__ gt,
    const float* __restrict__ theta,
    float* __restrict__ out)
{
    // grid: (WO/4/256, HO, NB). Each thread handles 4 consecutive x pixels.
    const int xg = blockIdx.x * 256 + threadIdx.x;   // 0..511 (x-group of 4)
    const int yo = blockIdx.y;
    const int b  = blockIdx.z;

    const float t0 = __ldg(theta + b * 6 + 0);
    const float t1 = __ldg(theta + b * 6 + 1);
    const float t2 = __ldg(theta + b * 6 + 2);
    const float t3 = __ldg(theta + b * 6 + 3);
    const float t4 = __ldg(theta + b * 6 + 4);
    const float t5 = __ldg(theta + b * 6 + 5);

    const float ys = (yo + 0.5f) * (2.0f / HO) - 1.0f;
    const float* __restrict__ g = gt + b * (HIN * WIN);

    // ---- boxy: thetay = [[1,0,0],[0,t4,t5]]; ix == xo exactly, wx = 0 ----
    // Only y-interp. iy depends solely on (b, yo): hoist everything.
    const float gyy  = fmaf(t4, ys, t5);
    const float iyy  = (fmaf(gyy, (float)HO, (float)HO) - 1.0f) * 0.5f;
    const float iy0f = floorf(iyy);
    const float wy1y = iyy - iy0f;
    const int   iy0y = (int)iy0f;
    const bool  ok0  = (iy0y >= 0) && (iy0y <= HO - 1);
    const bool  ok1  = (iy0y + 1 >= 0) && (iy0y + 1 <= HO - 1);
    const int   ry0  = (min(max(iy0y, 0), HO - 1)) >> 3;       // gt row (clamped, safe)
    const int   ry1  = (min(max(iy0y + 1, 0), HO - 1)) >> 3;
    const float wA   = ok0 ? (1.0f - wy1y) : 0.0f;
    const float wB   = ok1 ? wy1y : 0.0f;

    float4 vbox, vboxy;
    float* bo = reinterpret_cast<float*>(&vbox);
    float* by = reinterpret_cast<float*>(&vboxy);

    const float ys_t1_t2 = fmaf(t1, ys, t2);   // t1*ys + t2
    const float ys_t4_t5 = fmaf(t4, ys, t5);   // t4*ys + t5

    #pragma unroll
    for (int j = 0; j < 4; ++j) {
        const int   xo = xg * 4 + j;
        const float xs = (xo + 0.5f) * (2.0f / WO) - 1.0f;

        // ---- boxy (2 taps, column xo>>3; dedupes across j in the compiler) ----
        const int xc = xo >> 3;
        by[j] = wA * g[ry0 * WIN + xc] + wB * g[ry1 * WIN + xc];

        // ---- box: full affine bilinear ----
        const float gx = fmaf(t0, xs, ys_t1_t2);
        const float gy = fmaf(t3, xs, ys_t4_t5);
        const float ix = (fmaf(gx, (float)WO, (float)WO) - 1.0f) * 0.5f;
        const float iy = (fmaf(gy, (float)HO, (float)HO) - 1.0f) * 0.5f;
        const float ix0f = floorf(ix);
        const float iy0bf = floorf(iy);
        const float wx = ix - ix0f;
        const float wy = iy - iy0bf;
        const int ix0  = (int)ix0f;
        const int iyb0 = (int)iy0bf;

        float acc = 0.0f;
        // bounding-box early-out: any corner in range?
        if (ix0 >= -1 && ix0 <= WO - 1 && iyb0 >= -1 && iyb0 <= HO - 1) {
            const int x0c = (max(ix0, 0)) >> 3;
            const int x1c = (min(ix0 + 1, WO - 1)) >> 3;
            const int y0c = (max(iyb0, 0)) >> 3;
            const int y1c = (min(iyb0 + 1, HO - 1)) >> 3;
            const bool xv0 = (ix0 >= 0);
            const bool xv1 = (ix0 + 1 <= WO - 1);
            const bool yv0 = (iyb0 >= 0);
            const bool yv1 = (iyb0 + 1 <= HO - 1);
            const float w00 = (xv0 && yv0) ? (1.0f - wx) * (1.0f - wy) : 0.0f;
            const float w10 = (xv1 && yv0) ? wx * (1.0f - wy) : 0.0f;
            const float w01 = (xv0 && yv1) ? (1.0f - wx) * wy : 0.0f;
            const float w11 = (xv1 && yv1) ? wx * wy : 0.0f;
            acc = w00 * g[y0c * WIN + x0c]
                + w10 * g[y0c * WIN + x1c]
                + w01 * g[y1c * WIN + x0c]
                + w11 * g[y1c * WIN + x1c];
        }
        bo[j] = acc;
    }

    const long long pix = ((long long)b * HO + yo) * WO + xg * 4;
    float4* out_box  = reinterpret_cast<float4*>(out + pix);
    float4* out_boxy = reinterpret_cast<float4*>(out + (long long)NB * HO * WO + pix);
    *out_box  = vbox;
    *out_boxy = vboxy;
}
} // namespace

extern "C" void kernel_launch(void* const* d_in, const int* in_sizes, int n_in,
                              void* d_out, int out_size)
{
    const float* gt    = (const float*)d_in[0];
    const float* theta = (const float*)d_in[1];
    float* out = (float*)d_out;

    dim3 grid(WO / 4 / 256, HO, NB);   // (2, 1024, 8)
    stn_kernel<<<grid, 256>>>(gt, theta, out);
}

// round 2
// speedup vs baseline: 1.0164x; 1.0164x over previous
#include <cuda_runtime.h>
#include <cuda_bf16.h>

// STN_fixTheta: fused 8x nearest-upsample + dual bilinear grid_sample.
// gt: [8,1,128,256] f32, theta: [8,6] f32.
// out: box [8,1,1024,2048] f32 followed by boxy [8,1,1024,2048] f32.
//
// Key structure: ix is affine in output x with step exactly t0 (iy step t3/2),
// so each thread's 8-pixel segment is classified once as OOB / interior / edge.
// boxy (thetay = [[1,0,0],[0,t4,t5]]) has ix == xo exactly -> one value per
// 8-aligned group -> one lerp per thread.

namespace {
constexpr int NB  = 8;
constexpr int HIN = 128;
constexpr int WIN = 256;
constexpr int HO  = 1024;
constexpr int WO  = 2048;
constexpr int PX  = 8;     // pixels per thread (8-aligned group)

__constant__ float c_theta[NB * 6];

__global__ __launch_bounds__(256) void stn_kernel(
    const float* __restrict__ gt,
    float* __restrict__ out)
{
    const int t  = threadIdx.x;          // x-group index 0..255 (== gt column for boxy)
    const int yo = blockIdx.y;
    const int b  = blockIdx.z;
    const int xo0 = t * PX;

    const float t0 = c_theta[b * 6 + 0];
    const float t1 = c_theta[b * 6 + 1];
    const float t2 = c_theta[b * 6 + 2];
    const float t3 = c_theta[b * 6 + 3];
    const float t4 = c_theta[b * 6 + 4];
    const float t5 = c_theta[b * 6 + 5];

    const float ys = (yo + 0.5f) * (2.0f / HO) - 1.0f;
    const float* __restrict__ g = gt + b * (HIN * WIN);

    // ---------------- boxy: one value per thread ----------------
    const float gyy  = fmaf(t4, ys, t5);
    const float iyy  = (fmaf(gyy, (float)HO, (float)HO) - 1.0f) * 0.5f;
    const float iy0f = floorf(iyy);
    const float wyy  = iyy - iy0f;
    const int   iy0y = (int)iy0f;
    const bool  ok0  = (unsigned)iy0y < (unsigned)HO;
    const bool  ok1  = (unsigned)(iy0y + 1) < (unsigned)HO;
    float vy = 0.0f;
    if (ok0 | ok1) {
        const int   ry0 = (min(max(iy0y, 0), HO - 1)) >> 3;
        const int   ry1 = (min(max(iy0y + 1, 0), HO - 1)) >> 3;
        const float wA  = ok0 ? (1.0f - wyy) : 0.0f;
        const float wB  = ok1 ? wyy : 0.0f;
        vy = wA * g[ry0 * WIN + t] + wB * g[ry1 * WIN + t];
    }

    // ---------------- box: segment endpoints + classification ----------------
    const float xs0 = (xo0 + 0.5f) * (2.0f / WO) - 1.0f;
    const float gx0 = fmaf(t0, xs0, fmaf(t1, ys, t2));
    const float gy0 = fmaf(t3, xs0, fmaf(t4, ys, t5));
    const float ixb = (fmaf(gx0, (float)WO, (float)WO) - 1.0f) * 0.5f;
    const float iyb = (fmaf(gy0, (float)HO, (float)HO) - 1.0f) * 0.5f;
    const float sx  = t0;           // d ix / d xo
    const float sy  = t3 * 0.5f;    // d iy / d xo  (= t3 * HO / WO)

    const float ix7 = fmaf(7.0f, sx, ixb);
    const float iy7 = fmaf(7.0f, sy, iyb);
    const float ixmin = fminf(ixb, ix7), ixmax = fmaxf(ixb, ix7);
    const float iymin = fminf(iyb, iy7), iymax = fmaxf(iyb, iy7);

    float v[PX];

    if (ixmax < -1.0f || ixmin >= (float)WO || iymax < -1.0f || iymin >= (float)HO) {
        // all 4 corners invalid for every pixel in the group
        #pragma unroll
        for (int j = 0; j < PX; ++j) v[j] = 0.0f;
    } else if (ixmin >= 0.0f && ixmax < (float)(WO - 1) &&
               iymin >= 0.0f && iymax < (float)(HO - 1)) {
        // fully interior: no clamps, no validity predicates
        #pragma unroll
        for (int j = 0; j < PX; ++j) {
            const float ix  = fmaf((float)j, sx, ixb);
            const float iy  = fmaf((float)j, sy, iyb);
            const int   ix0 = __float2int_rd(ix);
            const int   iy0 = __float2int_rd(iy);
            const float wx  = ix - (float)ix0;
            const float wy  = iy - (float)iy0;
            const int x0 = ix0 >> 3;
            const int x1 = (ix0 + 1) >> 3;
            const int y0 = iy0 >> 3;
            const int y1 = (iy0 + 1) >> 3;
            const float v00 = g[(y0 << 8) + x0];
            const float v10 = g[(y0 << 8) + x1];
            const float v01 = g[(y1 << 8) + x0];
            const float v11 = g[(y1 << 8) + x1];
            const float a = fmaf(wx, v10 - v00, v00);
            const float c = fmaf(wx, v11 - v01, v01);
            v[j] = fmaf(wy, c - a, a);
        }
    } else {
        // edge/mixed group: general predicated path
        #pragma unroll
        for (int j = 0; j < PX; ++j) {
            const float ix  = fmaf((float)j, sx, ixb);
            const float iy  = fmaf((float)j, sy, iyb);
            const int   ix0 = __float2int_rd(ix);
            const int   iy0 = __float2int_rd(iy);
            const float wx  = ix - (float)ix0;
            const float wy  = iy - (float)iy0;
            const bool xv0 = (unsigned)ix0       < (unsigned)WO;
            const bool xv1 = (unsigned)(ix0 + 1) < (unsigned)WO;
            const bool yv0 = (unsigned)iy0       < (unsigned)HO;
            const bool yv1 = (unsigned)(iy0 + 1) < (unsigned)HO;
            const int x0 = (min(max(ix0, 0), WO - 1)) >> 3;
            const int x1 = (min(max(ix0 + 1, 0), WO - 1)) >> 3;
            const int y0 = (min(max(iy0, 0), HO - 1)) >> 3;
            const int y1 = (min(max(iy0 + 1, 0), HO - 1)) >> 3;
            const float w00 = (xv0 && yv0) ? (1.0f - wx) * (1.0f - wy) : 0.0f;
            const float w10 = (xv1 && yv0) ? wx * (1.0f - wy) : 0.0f;
            const float w01 = (xv0 && yv1) ? (1.0f - wx) * wy : 0.0f;
            const float w11 = (xv1 && yv1) ? wx * wy : 0.0f;
            v[j] = w00 * g[(y0 << 8) + x0]
                 + w10 * g[(y0 << 8) + x1]
                 + w01 * g[(y1 << 8) + x0]
                 + w11 * g[(y1 << 8) + x1];
        }
    }

    const long long pix = ((long long)b * HO + yo) * WO + xo0;
    float4* ob = reinterpret_cast<float4*>(out + pix);
    ob[0] = make_float4(v[0], v[1], v[2], v[3]);
    ob[1] = make_float4(v[4], v[5], v[6], v[7]);
    float4* oy = reinterpret_cast<float4*>(out + (long long)NB * HO * WO + pix);
    const float4 vy4 = make_float4(vy, vy, vy, vy);
    oy[0] = vy4;
    oy[1] = vy4;
}
} // namespace

extern "C" void kernel_launch(void* const* d_in, const int* in_sizes, int n_in,
                              void* d_out, int out_size)
{
    const float* gt    = (const float*)d_in[0];
    const float* theta = (const float*)d_in[1];
    float* out = (float*)d_out;

    cudaMemcpyToSymbolAsync(c_theta, theta, NB * 6 * sizeof(float), 0,
                            cudaMemcpyDeviceToDevice, 0);

    dim3 grid(1, HO, NB);
    stn_kernel<<<grid, 256>>>(gt, out);
}

// round 3
// speedup vs baseline: 1.1071x; 1.0892x over previous
#include <cuda_runtime.h>
#include <cuda_bf16.h>

// STN_fixTheta: fused 8x nearest-upsample + dual bilinear grid_sample.
// gt: [8,1,128,256] f32, theta: [8,6] f32.
// out: box [8,1,1024,2048] f32 followed by boxy [8,1,1024,2048] f32.

namespace {
constexpr int NB  = 8;
constexpr int HIN = 128;
constexpr int WIN = 256;
constexpr int HO  = 1024;
constexpr int WO  = 2048;
constexpr int PX  = 8;     // pixels per thread (8-aligned group)

// floor via 2^23 bias: no F2I/I2F cvt-pipe ops. Valid for |x| < ~4e6.
__device__ __forceinline__ void ffloor(float x, float& f, int& i) {
    const float MAGIC = 12582912.0f;            // 1.5 * 2^23
    float tt = x + MAGIC;                       // RNE to integer
    float r  = tt - MAGIC;
    int   ri = __float_as_int(tt) - 0x4B400000; // integer bits (wraps for negatives)
    if (r > x) { r -= 1.0f; ri -= 1; }          // round -> floor correction
    f = r; i = ri;
}

__global__ __launch_bounds__(256) void stn_kernel(
    const float* __restrict__ gt,
    const float* __restrict__ theta,
    float* __restrict__ out)
{
    const int t  = threadIdx.x;          // x-group 0..255 (== gt column for boxy)
    const int yo = blockIdx.y;
    const int b  = blockIdx.z;
    const int xo0 = t * PX;

    const float t0 = __ldg(theta + b * 6 + 0);
    const float t1 = __ldg(theta + b * 6 + 1);
    const float t2 = __ldg(theta + b * 6 + 2);
    const float t3 = __ldg(theta + b * 6 + 3);
    const float t4 = __ldg(theta + b * 6 + 4);
    const float t5 = __ldg(theta + b * 6 + 5);

    const float ys = (yo + 0.5f) * (2.0f / HO) - 1.0f;
    const float* __restrict__ g = gt + b * (HIN * WIN);

    // ---------------- boxy: one value per thread ----------------
    const float gyy  = fmaf(t4, ys, t5);
    const float iyy  = (fmaf(gyy, (float)HO, (float)HO) - 1.0f) * 0.5f;
    float iy0f; int iy0y;
    ffloor(iyy, iy0f, iy0y);
    const float wyy  = iyy - iy0f;
    const bool  ok0  = (unsigned)iy0y < (unsigned)HO;
    const bool  ok1  = (unsigned)(iy0y + 1) < (unsigned)HO;
    float vy = 0.0f;
    if (ok0 | ok1) {
        const int   ry0 = (min(max(iy0y, 0), HO - 1)) >> 3;
        const int   ry1 = (min(max(iy0y + 1, 0), HO - 1)) >> 3;
        const float wA  = ok0 ? (1.0f - wyy) : 0.0f;
        const float wB  = ok1 ? wyy : 0.0f;
        vy = wA * g[ry0 * WIN + t] + wB * g[ry1 * WIN + t];
    }

    // ---------------- box: segment classification ----------------
    const float xs0 = (xo0 + 0.5f) * (2.0f / WO) - 1.0f;
    const float gx0 = fmaf(t0, xs0, fmaf(t1, ys, t2));
    const float gy0 = fmaf(t3, xs0, fmaf(t4, ys, t5));
    const float ixb = (fmaf(gx0, (float)WO, (float)WO) - 1.0f) * 0.5f;
    const float iyb = (fmaf(gy0, (float)HO, (float)HO) - 1.0f) * 0.5f;
    const float sx  = t0;           // d ix / d xo
    const float sy  = t3 * 0.5f;    // d iy / d xo

    const float ix7 = fmaf(7.0f, sx, ixb);
    const float iy7 = fmaf(7.0f, sy, iyb);
    const float ixmin = fminf(ixb, ix7), ixmax = fmaxf(ixb, ix7);
    const float iymin = fminf(iyb, iy7), iymax = fmaxf(iyb, iy7);

    float v[PX];

    if (ixmax < -1.0f || ixmin >= (float)WO || iymax < -1.0f || iymin >= (float)HO) {
        #pragma unroll
        for (int j = 0; j < PX; ++j) v[j] = 0.0f;
    } else if (ixmin >= 0.0f && ixmax < (float)(WO - 1) &&
               iymin >= 0.0f && iymax < (float)(HO - 1)) {
        // fully interior: phase-separated addr -> load -> combine, 4-px chunks
        #pragma unroll
        for (int c = 0; c < 2; ++c) {
            int   o00[4], o10[4], o01[4], o11[4];
            float fwx[4], fwy[4];
            #pragma unroll
            for (int k = 0; k < 4; ++k) {
                const int   j  = c * 4 + k;
                const float ix = fmaf((float)j, sx, ixb);
                const float iy = fmaf((float)j, sy, iyb);
                float fx, fy; int ix0, iy0;
                ffloor(ix, fx, ix0);
                ffloor(iy, fy, iy0);
                fwx[k] = ix - fx;
                fwy[k] = iy - fy;
                const int x0 = ix0 >> 3;
                const int x1 = (ix0 + 1) >> 3;
                const int y0 = iy0 >> 3;
                const int y1 = (iy0 + 1) >> 3;
                o00[k] = (y0 << 8) + x0;
                o10[k] = (y0 << 8) + x1;
                o01[k] = (y1 << 8) + x0;
                o11[k] = (y1 << 8) + x1;
            }
            float l00[4], l10[4], l01[4], l11[4];
            #pragma unroll
            for (int k = 0; k < 4; ++k) {
                l00[k] = g[o00[k]];
                l10[k] = g[o10[k]];
                l01[k] = g[o01[k]];
                l11[k] = g[o11[k]];
            }
            #pragma unroll
            for (int k = 0; k < 4; ++k) {
                const float a  = fmaf(fwx[k], l10[k] - l00[k], l00[k]);
                const float cc = fmaf(fwx[k], l11[k] - l01[k], l01[k]);
                v[c * 4 + k] = fmaf(fwy[k], cc - a, a);
            }
        }
    } else {
        // edge/mixed group: general predicated path (rare)
        #pragma unroll
        for (int j = 0; j < PX; ++j) {
            const float ix = fmaf((float)j, sx, ixb);
            const float iy = fmaf((float)j, sy, iyb);
            float fx, fy; int ix0, iy0;
            ffloor(ix, fx, ix0);
            ffloor(iy, fy, iy0);
            const float wx = ix - fx;
            const float wy = iy - fy;
            const bool xv0 = (unsigned)ix0       < (unsigned)WO;
            const bool xv1 = (unsigned)(ix0 + 1) < (unsigned)WO;
            const bool yv0 = (unsigned)iy0       < (unsigned)HO;
            const bool yv1 = (unsigned)(iy0 + 1) < (unsigned)HO;
            const int x0 = (min(max(ix0, 0), WO - 1)) >> 3;
            const int x1 = (min(max(ix0 + 1, 0), WO - 1)) >> 3;
            const int y0 = (min(max(iy0, 0), HO - 1)) >> 3;
            const int y1 = (min(max(iy0 + 1, 0), HO - 1)) >> 3;
            const float w00 = (xv0 && yv0) ? (1.0f - wx) * (1.0f - wy) : 0.0f;
            const float w10 = (xv1 && yv0) ? wx * (1.0f - wy) : 0.0f;
            const float w01 = (xv0 && yv1) ? (1.0f - wx) * wy : 0.0f;
            const float w11 = (xv1 && yv1) ? wx * wy : 0.0f;
            v[j] = w00 * g[(y0 << 8) + x0]
                 + w10 * g[(y0 << 8) + x1]
                 + w01 * g[(y1 << 8) + x0]
                 + w11 * g[(y1 << 8) + x1];
        }
    }

    const long long pix = ((long long)b * HO + yo) * WO + xo0;
    float4* ob = reinterpret_cast<float4*>(out + pix);
    ob[0] = make_float4(v[0], v[1], v[2], v[3]);
    ob[1] = make_float4(v[4], v[5], v[6], v[7]);
    float4* oy = reinterpret_cast<float4*>(out + (long long)NB * HO * WO + pix);
    const float4 vy4 = make_float4(vy, vy, vy, vy);
    oy[0] = vy4;
    oy[1] = vy4;
}
} // namespace

extern "C" void kernel_launch(void* const* d_in, const int* in_sizes, int n_in,
                              void* d_out, int out_size)
{
    const float* gt    = (const float*)d_in[0];
    const float* theta = (const float*)d_in[1];
    float* out = (float*)d_out;

    dim3 grid(1, HO, NB);
    stn_kernel<<<grid, 256>>>(gt, theta, out);
}

// round 5
// speedup vs baseline: 1.2009x; 1.0848x over previous
#include <cuda_runtime.h>
#include <cuda_bf16.h>

// STN_fixTheta: fused 8x nearest-upsample + dual bilinear grid_sample.
// gt: [8,1,128,256] f32, theta: [8,6] f32.
// out: box [8,1,1024,2048] f32 followed by boxy [8,1,1024,2048] f32.
//
// 2D warp tiling: warp = 4 output rows x 8 lanes x 8 px, so each warp-level
// gather instruction touches only ~2-4 gt cache lines (vs ~16-32 for a 1D
// row layout with rotation-induced y scatter).

namespace {
constexpr int NB  = 8;
constexpr int HIN = 128;
constexpr int WIN = 256;
constexpr int HO  = 1024;
constexpr int WO  = 2048;
constexpr int PX  = 8;     // pixels per thread (8-aligned group)

// floor via 2^23 bias: no F2I/I2F cvt-pipe ops. Valid for |x| < ~4e6.
__device__ __forceinline__ void ffloor(float x, float& f, int& i) {
    const float MAGIC = 12582912.0f;            // 1.5 * 2^23
    float tt = x + MAGIC;                       // RNE to integer
    float r  = tt - MAGIC;
    int   ri = __float_as_int(tt) - 0x4B400000; // integer bits
    if (r > x) { r -= 1.0f; ri -= 1; }          // round -> floor correction
    f = r; i = ri;
}

__global__ __launch_bounds__(256) void stn_kernel(
    const float* __restrict__ gt,
    const float* __restrict__ theta,
    float* __restrict__ out)
{
    const int tid  = threadIdx.x;
    const int w    = tid >> 5;           // warp 0..7
    const int lane = tid & 31;
    const int lx   = lane & 7;           // 8 lanes in x
    const int ly   = lane >> 3;          // 4 rows in y
    const int wx   = w & 1;              // 2 warps in x
    const int wy   = w >> 1;             // 4 warps in y

    // block tile: 128 px wide x 16 rows
    const int xo0 = blockIdx.x * 128 + wx * 64 + lx * 8;
    const int yo  = blockIdx.y * 16  + wy * 4  + ly;
    const int b   = blockIdx.z;

    const float t0 = __ldg(theta + b * 6 + 0);
    const float t1 = __ldg(theta + b * 6 + 1);
    const float t2 = __ldg(theta + b * 6 + 2);
    const float t3 = __ldg(theta + b * 6 + 3);
    const float t4 = __ldg(theta + b * 6 + 4);
    const float t5 = __ldg(theta + b * 6 + 5);

    const float ys = (yo + 0.5f) * (2.0f / HO) - 1.0f;
    const float* __restrict__ g = gt + b * (HIN * WIN);

    // ---------------- boxy: one value per thread ----------------
    const float gyy  = fmaf(t4, ys, t5);
    const float iyy  = (fmaf(gyy, (float)HO, (float)HO) - 1.0f) * 0.5f;
    float iy0f; int iy0y;
    ffloor(iyy, iy0f, iy0y);
    const float wyy  = iyy - iy0f;
    const bool  ok0  = (unsigned)iy0y < (unsigned)HO;
    const bool  ok1  = (unsigned)(iy0y + 1) < (unsigned)HO;
    float vy = 0.0f;
    if (ok0 | ok1) {
        const int   xc  = xo0 >> 3;      // gt column (constant over 8 px)
        const int   ry0 = (min(max(iy0y, 0), HO - 1)) >> 3;
        const int   ry1 = (min(max(iy0y + 1, 0), HO - 1)) >> 3;
        const float wA  = ok0 ? (1.0f - wyy) : 0.0f;
        const float wB  = ok1 ? wyy : 0.0f;
        vy = wA * g[ry0 * WIN + xc] + wB * g[ry1 * WIN + xc];
    }

    // ---------------- box: segment classification ----------------
    const float xs0 = (xo0 + 0.5f) * (2.0f / WO) - 1.0f;
    const float gx0 = fmaf(t0, xs0, fmaf(t1, ys, t2));
    const float gy0 = fmaf(t3, xs0, fmaf(t4, ys, t5));
    const float ixb = (fmaf(gx0, (float)WO, (float)WO) - 1.0f) * 0.5f;
    const float iyb = (fmaf(gy0, (float)HO, (float)HO) - 1.0f) * 0.5f;
    const float sx  = t0;           // d ix / d xo
    const float sy  = t3 * 0.5f;    // d iy / d xo

    const float ix7 = fmaf(7.0f, sx, ixb);
    const float iy7 = fmaf(7.0f, sy, iyb);
    const float ixmin = fminf(ixb, ix7), ixmax = fmaxf(ixb, ix7);
    const float iymin = fminf(iyb, iy7), iymax = fmaxf(iyb, iy7);

    float v[PX];

    if (ixmax < -1.0f || ixmin >= (float)WO || iymax < -1.0f || iymin >= (float)HO) {
        #pragma unroll
        for (int j = 0; j < PX; ++j) v[j] = 0.0f;
    } else if (ixmin >= 0.0f && ixmax < (float)(WO - 1) &&
               iymin >= 0.0f && iymax < (float)(HO - 1)) {
        // fully interior: phase-separated addr -> load -> combine, 4-px chunks
        #pragma unroll
        for (int c = 0; c < 2; ++c) {
            int   o00[4], o10[4], o01[4], o11[4];
            float fwx[4], fwy[4];
            #pragma unroll
            for (int k = 0; k < 4; ++k) {
                const int   j  = c * 4 + k;
                const float ix = fmaf((float)j, sx, ixb);
                const float iy = fmaf((float)j, sy, iyb);
                float fx, fy; int ix0, iy0;
                ffloor(ix, fx, ix0);
                ffloor(iy, fy, iy0);
                fwx[k] = ix - fx;
                fwy[k] = iy - fy;
                const int x0 = ix0 >> 3;
                const int x1 = (ix0 + 1) >> 3;
                const int y0 = iy0 >> 3;
                const int y1 = (iy0 + 1) >> 3;
                o00[k] = (y0 << 8) + x0;
                o10[k] = (y0 << 8) + x1;
                o01[k] = (y1 << 8) + x0;
                o11[k] = (y1 << 8) + x1;
            }
            float l00[4], l10[4], l01[4], l11[4];
            #pragma unroll
            for (int k = 0; k < 4; ++k) {
                l00[k] = g[o00[k]];
                l10[k] = g[o10[k]];
                l01[k] = g[o01[k]];
                l11[k] = g[o11[k]];
            }
            #pragma unroll
            for (int k = 0; k < 4; ++k) {
                const float a  = fmaf(fwx[k], l10[k] - l00[k], l00[k]);
                const float cc = fmaf(fwx[k], l11[k] - l01[k], l01[k]);
                v[c * 4 + k] = fmaf(fwy[k], cc - a, a);
            }
        }
    } else {
        // edge/mixed group: general predicated path (rare)
        #pragma unroll
        for (int j = 0; j < PX; ++j) {
            const float ix = fmaf((float)j, sx, ixb);
            const float iy = fmaf((float)j, sy, iyb);
            float fx, fy; int ix0, iy0;
            ffloor(ix, fx, ix0);
            ffloor(iy, fy, iy0);
            const float wx = ix - fx;
            const float wy = iy - fy;
            const bool xv0 = (unsigned)ix0       < (unsigned)WO;
            const bool xv1 = (unsigned)(ix0 + 1) < (unsigned)WO;
            const bool yv0 = (unsigned)iy0       < (unsigned)HO;
            const bool yv1 = (unsigned)(iy0 + 1) < (unsigned)HO;
            const int x0 = (min(max(ix0, 0), WO - 1)) >> 3;
            const int x1 = (min(max(ix0 + 1, 0), WO - 1)) >> 3;
            const int y0 = (min(max(iy0, 0), HO - 1)) >> 3;
            const int y1 = (min(max(iy0 + 1, 0), HO - 1)) >> 3;
            const float w00 = (xv0 && yv0) ? (1.0f - wx) * (1.0f - wy) : 0.0f;
            const float w10 = (xv1 && yv0) ? wx * (1.0f - wy) : 0.0f;
            const float w01 = (xv0 && yv1) ? (1.0f - wx) * wy : 0.0f;
            const float w11 = (xv1 && yv1) ? wx * wy : 0.0f;
            v[j] = w00 * g[(y0 << 8) + x0]
                 + w10 * g[(y0 << 8) + x1]
                 + w01 * g[(y1 << 8) + x0]
                 + w11 * g[(y1 << 8) + x1];
        }
    }

    const long long pix = ((long long)b * HO + yo) * WO + xo0;
    float4* ob = reinterpret_cast<float4*>(out + pix);
    ob[0] = make_float4(v[0], v[1], v[2], v[3]);
    ob[1] = make_float4(v[4], v[5], v[6], v[7]);
    float4* oy = reinterpret_cast<float4*>(out + (long long)NB * HO * WO + pix);
    const float4 vy4 = make_float4(vy, vy, vy, vy);
    oy[0] = vy4;
    oy[1] = vy4;
}
} // namespace

extern "C" void kernel_launch(void* const* d_in, const int* in_sizes, int n_in,
                              void* d_out, int out_size)
{
    const float* gt    = (const float*)d_in[0];
    const float* theta = (const float*)d_in[1];
    float* out = (float*)d_out;

    dim3 grid(WO / 128, HO / 16, NB);   // (16, 64, 8)
    stn_kernel<<<grid, 256>>>(gt, theta, out);
}